// round 1
// baseline (speedup 1.0000x reference)
#include <cuda_runtime.h>

#define TT 512
#define BB 512
#define DD 16
#define HH 64
#define GG 192   // 3*H
#define RR 2     // batch rows per CTA
#define NT 192   // threads per CTA (one per gate-output row)

__device__ __forceinline__ unsigned long long fma2(unsigned long long a,
                                                   unsigned long long b,
                                                   unsigned long long c) {
    unsigned long long d;
    asm("fma.rn.f32x2 %0, %1, %2, %3;" : "=l"(d) : "l"(a), "l"(b), "l"(c));
    return d;
}
__device__ __forceinline__ float hadd2(unsigned long long a) {
    return __uint_as_float((unsigned)a) + __uint_as_float((unsigned)(a >> 32));
}
__device__ __forceinline__ float sigf(float x) {
    return __fdividef(1.f, 1.f + __expf(-x));
}
__device__ __forceinline__ float tanhfast(float x) {
    return __fdividef(2.f, 1.f + __expf(-2.f * x)) - 1.f;
}

__global__ __launch_bounds__(NT, 2)
void bigru_kernel(const float* __restrict__ x,
                  const float* __restrict__ w_ih_f, const float* __restrict__ w_hh_f,
                  const float* __restrict__ b_ih_f, const float* __restrict__ b_hh_f,
                  const float* __restrict__ w_ih_b,
                  const float* __restrict__ b_ih_b, const float* __restrict__ b_hh_b,
                  const float* __restrict__ fc_w,  const float* __restrict__ fc_b,
                  float* __restrict__ out)
{
    __shared__ __align__(16) float h_sh[2][RR][HH];
    __shared__ __align__(16) float x_sh[2][RR][DD];
    __shared__ float rz_sh[RR][2 * HH];
    __shared__ float red_sh[RR][HH];

    const int tid = threadIdx.x;
    const int b0  = blockIdx.x * RR;

    // ---- load this thread's gate-row weights into packed f32x2 registers ----
    ulonglong2 wh[HH / 4];   // 16 x (4 floats) of w_hh_f row `tid`
    ulonglong2 wi[DD / 4];   // 4  x (4 floats) of w_ih_f row `tid`
    {
        const ulonglong2* p = (const ulonglong2*)(w_hh_f + tid * HH);
        #pragma unroll
        for (int i = 0; i < HH / 4; i++) wh[i] = p[i];
        const ulonglong2* q = (const ulonglong2*)(w_ih_f + tid * DD);
        #pragma unroll
        for (int i = 0; i < DD / 4; i++) wi[i] = q[i];
    }
    const float bi = b_ih_f[tid];
    const float bh = b_hh_f[tid];

    // ---- init h = 0, stage x(t=0) ----
    if (tid < HH) {
        #pragma unroll
        for (int r = 0; r < RR; r++) h_sh[0][r][tid] = 0.f;
    }
    if (tid < RR * DD) {
        int r = tid / DD, k = tid % DD;
        x_sh[0][r][k] = x[((size_t)(b0 + r) * TT) * DD + k];
    }
    __syncthreads();

    int p = 0;
    for (int t = 0; t < TT; ++t) {
        // prefetch x(t+1) into registers (latency hidden by the dot compute)
        float4 xn = make_float4(0.f, 0.f, 0.f, 0.f);
        if (tid < RR * 4 && t + 1 < TT) {
            int r = tid >> 2, q = tid & 3;
            xn = *(const float4*)(x + ((size_t)(b0 + r) * TT + (t + 1)) * DD + q * 4);
        }

        // ---- dot products for both rows (packed f32x2 FMAs) ----
        float vh[RR], vx[RR];
        #pragma unroll
        for (int r = 0; r < RR; r++) {
            const ulonglong2* hp = (const ulonglong2*)&h_sh[p][r][0];
            unsigned long long a0 = 0ull, a1 = 0ull;
            #pragma unroll
            for (int i = 0; i < HH / 4; i++) {
                ulonglong2 hv = hp[i];
                a0 = fma2(wh[i].x, hv.x, a0);
                a1 = fma2(wh[i].y, hv.y, a1);
            }
            const ulonglong2* xp = (const ulonglong2*)&x_sh[p][r][0];
            unsigned long long c0 = 0ull, c1 = 0ull;
            #pragma unroll
            for (int i = 0; i < DD / 4; i++) {
                ulonglong2 xv = xp[i];
                c0 = fma2(wi[i].x, xv.x, c0);
                c1 = fma2(wi[i].y, xv.y, c1);
            }
            vh[r] = hadd2(a0) + hadd2(a1);
            vx[r] = hadd2(c0) + hadd2(c1);
        }

        // r/z threads: activation + publish
        if (tid < 2 * HH) {
            #pragma unroll
            for (int r = 0; r < RR; r++)
                rz_sh[r][tid] = sigf(vh[r] + vx[r] + bi + bh);
        }
        __syncthreads();

        // n threads: finalize gate n and the hidden-state update
        if (tid >= 2 * HH) {
            int j = tid - 2 * HH;
            #pragma unroll
            for (int r = 0; r < RR; r++) {
                float rr = rz_sh[r][j];
                float zz = rz_sh[r][HH + j];
                float nn = tanhfast(vx[r] + bi + rr * (vh[r] + bh));
                float ho = h_sh[p][r][j];
                h_sh[p ^ 1][r][j] = (1.f - zz) * nn + zz * ho;
            }
        } else if (tid < RR * 4 && t + 1 < TT) {
            int r = tid >> 2, q = tid & 3;
            *(float4*)&x_sh[p ^ 1][r][q * 4] = xn;
        }
        __syncthreads();
        p ^= 1;
    }

    // ---- epilogue: backward GRU is ONE step from h=0 on x[:,T-1,:]; then fc ----
    if (tid < 2 * HH) {
        int r = tid >> 6, j = tid & 63;
        int b = b0 + r;
        const float* xl = x + ((size_t)b * TT + (TT - 1)) * DD;
        float xv[DD];
        #pragma unroll
        for (int k = 0; k < DD; k++) xv[k] = __ldg(xl + k);

        float ar  = __ldg(b_ih_b + j)           + __ldg(b_hh_b + j);
        float az  = __ldg(b_ih_b + HH + j)      + __ldg(b_hh_b + HH + j);
        float anx = __ldg(b_ih_b + 2 * HH + j);
        float anh = __ldg(b_hh_b + 2 * HH + j);
        const float* wr = w_ih_b + (size_t)j * DD;
        const float* wz = w_ih_b + (size_t)(HH + j) * DD;
        const float* wn = w_ih_b + (size_t)(2 * HH + j) * DD;
        #pragma unroll
        for (int k = 0; k < DD; k++) {
            ar  += __ldg(wr + k) * xv[k];
            az  += __ldg(wz + k) * xv[k];
            anx += __ldg(wn + k) * xv[k];
        }
        float rb = sigf(ar);
        float zb = sigf(az);
        float nb = tanhfast(anx + rb * anh);
        float hb = (1.f - zb) * nb;   // h_prev = 0

        float part = h_sh[p][r][j] * __ldg(fc_w + j) + hb * __ldg(fc_w + HH + j);
        red_sh[r][j] = part;
    }
    __syncthreads();
    if (tid < RR) {
        float s = __ldg(fc_b);
        #pragma unroll
        for (int k = 0; k < HH; k++) s += red_sh[tid][k];
        out[b0 + tid] = s;
    }
}

extern "C" void kernel_launch(void* const* d_in, const int* in_sizes, int n_in,
                              void* d_out, int out_size)
{
    const float* x      = (const float*)d_in[0];
    const float* w_ih_f = (const float*)d_in[1];
    const float* w_hh_f = (const float*)d_in[2];
    const float* b_ih_f = (const float*)d_in[3];
    const float* b_hh_f = (const float*)d_in[4];
    const float* w_ih_b = (const float*)d_in[5];
    /* d_in[6] = w_hh_b: unused — backward direction starts from h=0, so its
       recurrent term reduces to b_hh_b only. */
    const float* b_ih_b = (const float*)d_in[7];
    const float* b_hh_b = (const float*)d_in[8];
    const float* fc_w   = (const float*)d_in[9];
    const float* fc_b   = (const float*)d_in[10];

    bigru_kernel<<<BB / RR, NT>>>(x, w_ih_f, w_hh_f, b_ih_f, b_hh_f,
                                  w_ih_b, b_ih_b, b_hh_b, fc_w, fc_b,
                                  (float*)d_out);
}